// round 2
// baseline (speedup 1.0000x reference)
#include <cuda_runtime.h>
#include <cstdint>
#include <cstddef>

// Problem constants
#define NTOK 8192
#define NEXP 64
#define MDIM 2048
#define CAP  256
#define SEC  134217728LL   // 8192*64*256

// ---------------- device scratch (static, no allocation) ----------------
__device__ float g_logits[NTOK * NEXP];      // 2 MB
__device__ int   g_e1[NTOK];
__device__ int   g_e2[NTOK];
__device__ float g_g1[NTOK];
__device__ float g_g2[NTOK];
__device__ int   g_loc1[NTOK];
__device__ int   g_loc2[NTOK];
__device__ int   g_cnt1[NEXP];
__device__ float g_me_part[(NTOK / 8) * NEXP];  // 1024 x 64 partial gate sums

// ---------------- threefry2x32 (JAX-exact, key = (0, 42)) ----------------
__device__ __forceinline__ uint2 threefry2x32_k42(uint32_t x0, uint32_t x1) {
    const uint32_t k0 = 0u, k1 = 42u;
    const uint32_t k2 = k0 ^ k1 ^ 0x1BD11BDAu;
    x0 += k0; x1 += k1;
#define TFR(r) { x0 += x1; x1 = (x1 << (r)) | (x1 >> (32 - (r))); x1 ^= x0; }
    TFR(13) TFR(15) TFR(26) TFR(6)   x0 += k1; x1 += k2 + 1u;
    TFR(17) TFR(29) TFR(16) TFR(24)  x0 += k2; x1 += k0 + 2u;
    TFR(13) TFR(15) TFR(26) TFR(6)   x0 += k0; x1 += k1 + 3u;
    TFR(17) TFR(29) TFR(16) TFR(24)  x0 += k1; x1 += k2 + 4u;
    TFR(13) TFR(15) TFR(26) TFR(6)   x0 += k2; x1 += k0 + 5u;
#undef TFR
    return make_uint2(x0, x1);
}

// JAX *partitionable* threefry (default since jax 0.4.36):
// counter = 64-bit flat index -> pair (hi, lo) = (0, flat); 32-bit output is
// the XOR fold of the two threefry output lanes.
__device__ __forceinline__ uint32_t gumbel_bits(uint32_t flat) {
    uint2 r = threefry2x32_k42(0u, flat);
    return r.x ^ r.y;
}

__device__ __forceinline__ float gumbel_from_flat(uint32_t flat) {
    uint32_t bits = gumbel_bits(flat);
    float u = __uint_as_float((bits >> 9) | 0x3f800000u) - 1.0f;
    const float tiny = 1.17549435082228751e-38f;  // finfo(f32).tiny
    u = u * (1.0f - tiny) + tiny;                 // (1-tiny) folds to 1.0f, same as JAX
    u = fmaxf(tiny, u);
    return -logf(-logf(u));
}

// ---------------- Kernel 1: logits = x @ wg^T  (fp32 SGEMM, 64x64 tiles) ----------------
__global__ void __launch_bounds__(256) gemm_kernel(const float* __restrict__ X,
                                                   const float* __restrict__ W) {
    __shared__ float sx[32][68];  // [k][token], row stride 272B (16B aligned)
    __shared__ float sw[32][68];  // [k][expert]
    const int tid = threadIdx.x;
    const int tb  = blockIdx.x * 64;
    const int tx  = tid & 15;   // expert quad
    const int ty  = tid >> 4;   // token quad

    float acc[4][4];
#pragma unroll
    for (int i = 0; i < 4; i++)
#pragma unroll
        for (int j = 0; j < 4; j++) acc[i][j] = 0.f;

    for (int kk = 0; kk < MDIM; kk += 32) {
#pragma unroll
        for (int i = 0; i < 2; i++) {
            int idx = tid + 256 * i;        // 0..511
            int row = idx >> 3;             // 0..63
            int kq  = (idx & 7) * 4;        // 0,4,...,28
            float4 vx = *(const float4*)&X[(size_t)(tb + row) * MDIM + kk + kq];
            sx[kq + 0][row] = vx.x; sx[kq + 1][row] = vx.y;
            sx[kq + 2][row] = vx.z; sx[kq + 3][row] = vx.w;
            float4 vw = *(const float4*)&W[(size_t)row * MDIM + kk + kq];
            sw[kq + 0][row] = vw.x; sw[kq + 1][row] = vw.y;
            sw[kq + 2][row] = vw.z; sw[kq + 3][row] = vw.w;
        }
        __syncthreads();
#pragma unroll
        for (int k = 0; k < 32; k++) {
            float4 a = *(const float4*)&sx[k][ty * 4];
            float4 b = *(const float4*)&sw[k][tx * 4];
            float av[4] = {a.x, a.y, a.z, a.w};
            float bv[4] = {b.x, b.y, b.z, b.w};
#pragma unroll
            for (int i = 0; i < 4; i++)
#pragma unroll
                for (int j = 0; j < 4; j++) acc[i][j] += av[i] * bv[j];
        }
        __syncthreads();
    }
#pragma unroll
    for (int i = 0; i < 4; i++)
#pragma unroll
        for (int j = 0; j < 4; j++)
            g_logits[(size_t)(tb + ty * 4 + i) * NEXP + tx * 4 + j] = acc[i][j];
}

// ---------------- Kernel 2: per-token softmax, argmax1, gumbel, argmax2 ----------------
__global__ void __launch_bounds__(256) pertoken_kernel() {
    __shared__ float sg[8][NEXP];
    const unsigned FULL = 0xffffffffu;
    const int w = threadIdx.x >> 5;
    const int lane = threadIdx.x & 31;
    const int t = blockIdx.x * 8 + w;

    float2 lg = *(const float2*)&g_logits[(size_t)t * NEXP + lane * 2];

    // row max (for softmax)
    float vmax = fmaxf(lg.x, lg.y);
#pragma unroll
    for (int o = 16; o; o >>= 1) vmax = fmaxf(vmax, __shfl_xor_sync(FULL, vmax, o));

    // argmax1 (first index on ties)
    float bv; int bi;
    if (lg.x >= lg.y) { bv = lg.x; bi = lane * 2; } else { bv = lg.y; bi = lane * 2 + 1; }
#pragma unroll
    for (int o = 16; o; o >>= 1) {
        float ov = __shfl_xor_sync(FULL, bv, o);
        int   oi = __shfl_xor_sync(FULL, bi, o);
        if (ov > bv || (ov == bv && oi < bi)) { bv = ov; bi = oi; }
    }
    const int e1 = bi;

    // softmax
    float ex0 = expf(lg.x - vmax), ex1 = expf(lg.y - vmax);
    float ssum = ex0 + ex1;
#pragma unroll
    for (int o = 16; o; o >>= 1) ssum += __shfl_xor_sync(FULL, ssum, o);
    float gx = ex0 / ssum, gy = ex1 / ssum;
    sg[w][lane * 2] = gx; sg[w][lane * 2 + 1] = gy;

    // gumbel-perturbed logits, mask e1 to -inf
    uint32_t f0 = (uint32_t)t * NEXP + lane * 2;
    float n0 = lg.x + gumbel_from_flat(f0);
    float n1 = lg.y + gumbel_from_flat(f0 + 1);
    if (lane * 2     == e1) n0 = -__int_as_float(0x7f800000);  // -inf
    if (lane * 2 + 1 == e1) n1 = -__int_as_float(0x7f800000);

    float cv; int ci;
    if (n0 >= n1) { cv = n0; ci = lane * 2; } else { cv = n1; ci = lane * 2 + 1; }
#pragma unroll
    for (int o = 16; o; o >>= 1) {
        float ov = __shfl_xor_sync(FULL, cv, o);
        int   oi = __shfl_xor_sync(FULL, ci, o);
        if (ov > cv || (ov == cv && oi < ci)) { cv = ov; ci = oi; }
    }
    const int e2 = ci;

    float ge1 = __shfl_sync(FULL, (e1 & 1) ? gy : gx, e1 >> 1);
    float ge2 = __shfl_sync(FULL, (e2 & 1) ? gy : gx, e2 >> 1);

    if (lane == 0) {
        g_e1[t] = e1; g_e2[t] = e2;
        g_g1[t] = ge1; g_g2[t] = ge2;
    }
    __syncthreads();
    // deterministic per-block gate column sums (for me)
    if (threadIdx.x < NEXP) {
        float s = 0.f;
#pragma unroll
        for (int i = 0; i < 8; i++) s += sg[i][threadIdx.x];
        g_me_part[blockIdx.x * NEXP + threadIdx.x] = s;
    }
}

// ---------------- Kernel 3/4: per-expert running prefix (cumsum over tokens) ----------------
// pass 0: scan g_e1 -> g_loc1 (offset base 0), write g_cnt1
// pass 1: scan g_e2 -> g_loc2 (offset base = g_cnt1[E])
__global__ void __launch_bounds__(256) cumsum_kernel(int pass) {
    const unsigned FULL = 0xffffffffu;
    const int Eid = blockIdx.x;
    const int w = threadIdx.x >> 5;
    const int lane = threadIdx.x & 31;
    __shared__ int wsum[8];

    const int* __restrict__ eArr = (pass == 0) ? g_e1 : g_e2;
    int* __restrict__ locArr     = (pass == 0) ? g_loc1 : g_loc2;

    int offset = (pass == 0) ? 0 : g_cnt1[Eid];

    for (int base = 0; base < NTOK; base += 256) {
        int f = (eArr[base + threadIdx.x] == Eid) ? 1 : 0;
        unsigned b = __ballot_sync(FULL, f);
        int wpre = __popc(b & ((1u << lane) - 1u));
        if (lane == 0) wsum[w] = __popc(b);
        __syncthreads();
        int wbase = 0, tot = 0;
#pragma unroll
        for (int i = 0; i < 8; i++) { if (i < w) wbase += wsum[i]; tot += wsum[i]; }
        if (f) locArr[base + threadIdx.x] = offset + wbase + wpre;
        offset += tot;
        __syncthreads();
    }
    if (pass == 0 && threadIdx.x == 0) g_cnt1[Eid] = offset;
}

// ---------------- Kernel 5: zero-fill entire output ----------------
__global__ void __launch_bounds__(256) zerofill_kernel(float* __restrict__ out, int n) {
    int n4 = n >> 2;
    float4* o4 = (float4*)out;
    float4 z = make_float4(0.f, 0.f, 0.f, 0.f);
    for (int i = blockIdx.x * blockDim.x + threadIdx.x; i < n4; i += gridDim.x * blockDim.x)
        o4[i] = z;
    if (blockIdx.x == 0 && threadIdx.x < (n & 3))
        out[(size_t)n4 * 4 + threadIdx.x] = 0.f;
}

// ---------------- Kernel 6: scatter combine weights + dispatch mask ----------------
__global__ void __launch_bounds__(256) scatter_kernel(float* __restrict__ out, int out_size) {
    const int t = blockIdx.x * 256 + threadIdx.x;
    if (t >= NTOK) return;
    const int e1 = g_e1[t], e2 = g_e2[t];
    const int l1 = g_loc1[t], l2 = g_loc2[t];
    const bool k1 = (l1 < CAP), k2 = (l2 < CAP);
    const float g1 = k1 ? g_g1[t] : 0.f;
    const float g2 = k2 ? g_g2[t] : 0.f;
    const float denom = fmaxf(g1 + g2, 1.1920928955078125e-7f);  // finfo(f32).eps

    const bool haveComb = ((long long)out_size >= 1 + SEC);
    const bool haveDisp = ((long long)out_size >= 1 + 2 * SEC);
    float* comb = out + 1;
    float* disp = out + 1 + SEC;

    if (k1) {
        size_t idx = (size_t)t * (NEXP * CAP) + (size_t)e1 * CAP + l1;
        if (haveComb) comb[idx] = g1 / denom;
        if (haveDisp) disp[idx] = 1.0f;
    }
    if (k2) {
        size_t idx = (size_t)t * (NEXP * CAP) + (size_t)e2 * CAP + l2;
        if (haveComb) comb[idx] = g2 / denom;
        if (haveDisp) disp[idx] = 1.0f;
    }
}

// ---------------- Kernel 7: l_aux ----------------
__global__ void __launch_bounds__(64) laux_kernel(float* __restrict__ out) {
    __shared__ float sm[NEXP];
    const int e = threadIdx.x;
    float s = 0.f;
    for (int b = 0; b < NTOK / 8; b++) s += g_me_part[b * NEXP + e];
    float me = s * (1.0f / NTOK);
    float ce = (float)g_cnt1[e] * (1.0f / NTOK);
    sm[e] = me * ce;
    __syncthreads();
    if (e == 0) {
        float tot = 0.f;
        for (int i = 0; i < NEXP; i++) tot += sm[i];
        out[0] = tot * (float)NEXP;  // mean over experts * e^2 == sum * e
    }
}

// ---------------- launch ----------------
extern "C" void kernel_launch(void* const* d_in, const int* in_sizes, int n_in,
                              void* d_out, int out_size) {
    const float* x  = (const float*)d_in[0];
    const float* wg = (const float*)d_in[1];
    float* out = (float*)d_out;

    gemm_kernel<<<NTOK / 64, 256>>>(x, wg);
    pertoken_kernel<<<NTOK / 8, 256>>>();
    cumsum_kernel<<<NEXP, 256>>>(0);
    cumsum_kernel<<<NEXP, 256>>>(1);
    zerofill_kernel<<<4096, 256>>>(out, out_size);
    scatter_kernel<<<NTOK / 256, 256>>>(out, out_size);
    laux_kernel<<<1, 64>>>(out);
}

// round 3
// speedup vs baseline: 1.1564x; 1.1564x over previous
#include <cuda_runtime.h>
#include <cstdint>
#include <cstddef>

#define NTOK 8192
#define NEXP 64
#define MDIM 2048
#define CAP  256
#define SEC  134217728LL   // 8192*64*256

#define GEMM_BLOCKS 128
#define TOTAL_BLOCKS 4096
#define FILL_BLOCKS (TOTAL_BLOCKS - GEMM_BLOCKS)

// ---------------- device scratch ----------------
__device__ int    g_e12[NTOK];           // e1 | e2<<8
__device__ float2 g_g12[NTOK];           // raw gate values (g1, g2)
__device__ int    g_loc1[NTOK];
__device__ int    g_loc2[NTOK];          // partial (needs +cnt1[e2])
__device__ int    g_cnt1[NEXP];
__device__ float  g_me_part[GEMM_BLOCKS * NEXP];

// ---------------- threefry2x32, key (0,42), partitionable fold ----------------
__device__ __forceinline__ uint2 threefry2x32_k42(uint32_t x0, uint32_t x1) {
    const uint32_t k0 = 0u, k1 = 42u;
    const uint32_t k2 = k0 ^ k1 ^ 0x1BD11BDAu;
    x0 += k0; x1 += k1;
#define TFR(r) { x0 += x1; x1 = (x1 << (r)) | (x1 >> (32 - (r))); x1 ^= x0; }
    TFR(13) TFR(15) TFR(26) TFR(6)   x0 += k1; x1 += k2 + 1u;
    TFR(17) TFR(29) TFR(16) TFR(24)  x0 += k2; x1 += k0 + 2u;
    TFR(13) TFR(15) TFR(26) TFR(6)   x0 += k0; x1 += k1 + 3u;
    TFR(17) TFR(29) TFR(16) TFR(24)  x0 += k1; x1 += k2 + 4u;
    TFR(13) TFR(15) TFR(26) TFR(6)   x0 += k2; x1 += k0 + 5u;
#undef TFR
    return make_uint2(x0, x1);
}

__device__ __forceinline__ float gumbel_from_flat(uint32_t flat) {
    uint2 r = threefry2x32_k42(0u, flat);
    uint32_t bits = r.x ^ r.y;
    float u = __uint_as_float((bits >> 9) | 0x3f800000u) - 1.0f;
    const float tiny = 1.17549435082228751e-38f;
    u = u * (1.0f - tiny) + tiny;
    u = fmaxf(tiny, u);
    return -logf(-logf(u));
}

// ---------------- Kernel 1: fused GEMM + gating (blocks 0..127) + zero-fill (rest) ----
__global__ void __launch_bounds__(256) fused_kernel(const float* __restrict__ X,
                                                    const float* __restrict__ W,
                                                    float* __restrict__ out, int out_size) {
    const int bid = blockIdx.x;
    const int tid = threadIdx.x;

    if (bid >= GEMM_BLOCKS) {
        // -------- zero-fill path --------
        int n4 = out_size >> 2;
        float4* o4 = (float4*)out;
        float4 z = make_float4(0.f, 0.f, 0.f, 0.f);
        for (long long i = (long long)(bid - GEMM_BLOCKS) * 256 + tid; i < n4;
             i += (long long)FILL_BLOCKS * 256)
            o4[i] = z;
        if (bid == GEMM_BLOCKS && tid < (out_size & 3))
            out[(size_t)n4 * 4 + tid] = 0.f;
        return;
    }

    // -------- GEMM path: 64 tokens x 64 experts --------
    __shared__ float pool[4672];                       // 18.7 KB
    float (*sx)[68] = (float(*)[68])pool;              // 32 x 68
    float (*sw)[68] = (float(*)[68])(pool + 32 * 68);  // 32 x 68
    float* lgs   = pool;                               // 64 x 65 (reuse)
    float* gpart = pool + 64 * 65;                     // 8 x 64

    const int tb = bid * 64;
    const int tx = tid & 15;   // expert quad
    const int ty = tid >> 4;   // token quad

    float acc[4][4];
#pragma unroll
    for (int i = 0; i < 4; i++)
#pragma unroll
        for (int j = 0; j < 4; j++) acc[i][j] = 0.f;

    for (int kk = 0; kk < MDIM; kk += 32) {
#pragma unroll
        for (int i = 0; i < 2; i++) {
            int idx = tid + 256 * i;
            int row = idx >> 3;
            int kq  = (idx & 7) * 4;
            float4 vx = *(const float4*)&X[(size_t)(tb + row) * MDIM + kk + kq];
            sx[kq + 0][row] = vx.x; sx[kq + 1][row] = vx.y;
            sx[kq + 2][row] = vx.z; sx[kq + 3][row] = vx.w;
            float4 vw = *(const float4*)&W[(size_t)row * MDIM + kk + kq];
            sw[kq + 0][row] = vw.x; sw[kq + 1][row] = vw.y;
            sw[kq + 2][row] = vw.z; sw[kq + 3][row] = vw.w;
        }
        __syncthreads();
#pragma unroll
        for (int k = 0; k < 32; k++) {
            float4 a = *(const float4*)&sx[k][ty * 4];
            float4 b = *(const float4*)&sw[k][tx * 4];
            float av[4] = {a.x, a.y, a.z, a.w};
            float bv[4] = {b.x, b.y, b.z, b.w};
#pragma unroll
            for (int i = 0; i < 4; i++)
#pragma unroll
                for (int j = 0; j < 4; j++) acc[i][j] += av[i] * bv[j];
        }
        __syncthreads();
    }

    // stash logits into smem (padded row = 65)
#pragma unroll
    for (int i = 0; i < 4; i++)
#pragma unroll
        for (int j = 0; j < 4; j++)
            lgs[(ty * 4 + i) * 65 + tx * 4 + j] = acc[i][j];
    __syncthreads();

    // -------- gating: warp w handles tokens w*8 .. w*8+7 --------
    const unsigned FULL = 0xffffffffu;
    const int w = tid >> 5;
    const int lane = tid & 31;
    float accx = 0.f, accy = 0.f;   // per-expert gate sums (experts 2*lane, 2*lane+1)

#pragma unroll 1
    for (int k = 0; k < 8; k++) {
        const int tl = w * 8 + k;
        const int t  = tb + tl;
        float l0 = lgs[tl * 65 + lane * 2];
        float l1 = lgs[tl * 65 + lane * 2 + 1];

        float vmax = fmaxf(l0, l1);
#pragma unroll
        for (int o = 16; o; o >>= 1) vmax = fmaxf(vmax, __shfl_xor_sync(FULL, vmax, o));

        float bv; int bi;
        if (l0 >= l1) { bv = l0; bi = lane * 2; } else { bv = l1; bi = lane * 2 + 1; }
#pragma unroll
        for (int o = 16; o; o >>= 1) {
            float ov = __shfl_xor_sync(FULL, bv, o);
            int   oi = __shfl_xor_sync(FULL, bi, o);
            if (ov > bv || (ov == bv && oi < bi)) { bv = ov; bi = oi; }
        }
        const int e1 = bi;

        float ex0 = expf(l0 - vmax), ex1 = expf(l1 - vmax);
        float ssum = ex0 + ex1;
#pragma unroll
        for (int o = 16; o; o >>= 1) ssum += __shfl_xor_sync(FULL, ssum, o);
        float gx = ex0 / ssum, gy = ex1 / ssum;
        accx += gx; accy += gy;

        uint32_t f0 = (uint32_t)t * NEXP + lane * 2;
        float n0 = l0 + gumbel_from_flat(f0);
        float n1 = l1 + gumbel_from_flat(f0 + 1);
        if (lane * 2     == e1) n0 = -__int_as_float(0x7f800000);
        if (lane * 2 + 1 == e1) n1 = -__int_as_float(0x7f800000);

        float cv; int ci;
        if (n0 >= n1) { cv = n0; ci = lane * 2; } else { cv = n1; ci = lane * 2 + 1; }
#pragma unroll
        for (int o = 16; o; o >>= 1) {
            float ov = __shfl_xor_sync(FULL, cv, o);
            int   oi = __shfl_xor_sync(FULL, ci, o);
            if (ov > cv || (ov == cv && oi < ci)) { cv = ov; ci = oi; }
        }
        const int e2 = ci;

        float ge1 = __shfl_sync(FULL, (e1 & 1) ? gy : gx, e1 >> 1);
        float ge2 = __shfl_sync(FULL, (e2 & 1) ? gy : gx, e2 >> 1);

        if (lane == 0) {
            g_e12[t] = e1 | (e2 << 8);
            g_g12[t] = make_float2(ge1, ge2);
        }
    }

    gpart[w * 64 + lane * 2]     = accx;
    gpart[w * 64 + lane * 2 + 1] = accy;
    __syncthreads();
    if (tid < NEXP) {
        float s = 0.f;
#pragma unroll
        for (int i = 0; i < 8; i++) s += gpart[i * 64 + tid];
        g_me_part[bid * NEXP + tid] = s;
    }
}

// ---------------- Kernel 2: single-pass dual cumsum (rank1 + rank2) ----------------
__global__ void __launch_bounds__(256) cumsum_kernel() {
    const unsigned FULL = 0xffffffffu;
    const int Eid = blockIdx.x;
    const int tid = threadIdx.x;
    const int w = tid >> 5;
    const int lane = tid & 31;
    __shared__ int wtot[8];

    int off1 = 0, off2 = 0;

    for (int base = 0; base < NTOK; base += 1024) {
        int4 v = *(const int4*)&g_e12[base + tid * 4];
        int va[4] = {v.x, v.y, v.z, v.w};
        int f1[4], f2[4], p1[4], p2[4];
        int c1 = 0, c2 = 0;
#pragma unroll
        for (int k = 0; k < 4; k++) {
            f1[k] = ((va[k] & 0xff) == Eid);
            f2[k] = (((va[k] >> 8) & 0xff) == Eid);
            p1[k] = c1; p2[k] = c2;
            c1 += f1[k]; c2 += f2[k];
        }
        int c = c1 | (c2 << 16);
        int incl = c;
#pragma unroll
        for (int o = 1; o < 32; o <<= 1) {
            int n = __shfl_up_sync(FULL, incl, o);
            if (lane >= o) incl += n;
        }
        int excl = incl - c;
        if (lane == 31) wtot[w] = incl;
        __syncthreads();
        int wb = 0, bt = 0;
#pragma unroll
        for (int i = 0; i < 8; i++) { int t = wtot[i]; if (i < w) wb += t; bt += t; }
        int pk = wb + excl;
        int b1 = off1 + (pk & 0xffff);
        int b2 = off2 + ((pk >> 16) & 0xffff);
#pragma unroll
        for (int k = 0; k < 4; k++) {
            int tok = base + tid * 4 + k;
            if (f1[k]) g_loc1[tok] = b1 + p1[k];
            if (f2[k]) g_loc2[tok] = b2 + p2[k];
        }
        off1 += bt & 0xffff;
        off2 += (bt >> 16) & 0xffff;
        __syncthreads();
    }
    if (tid == 0) g_cnt1[Eid] = off1;
}

// ---------------- Kernel 3: scatter + l_aux ----------------
__global__ void __launch_bounds__(256) scatter_laux_kernel(float* __restrict__ out, int out_size) {
    const int t = blockIdx.x * 256 + threadIdx.x;
    if (t < NTOK) {
        int e12 = g_e12[t];
        const int e1 = e12 & 0xff, e2 = (e12 >> 8) & 0xff;
        const int l1 = g_loc1[t];
        const int l2 = g_loc2[t] + g_cnt1[e2];
        const bool k1 = (l1 < CAP), k2 = (l2 < CAP);
        float2 g12 = g_g12[t];
        const float g1 = k1 ? g12.x : 0.f;
        const float g2 = k2 ? g12.y : 0.f;
        const float denom = fmaxf(g1 + g2, 1.1920928955078125e-7f);

        const bool haveComb = ((long long)out_size >= 1 + SEC);
        const bool haveDisp = ((long long)out_size >= 1 + 2 * SEC);
        float* comb = out + 1;
        float* disp = out + 1 + SEC;

        if (k1) {
            size_t idx = (size_t)t * (NEXP * CAP) + (size_t)e1 * CAP + l1;
            if (haveComb) comb[idx] = g1 / denom;
            if (haveDisp) disp[idx] = 1.0f;
        }
        if (k2) {
            size_t idx = (size_t)t * (NEXP * CAP) + (size_t)e2 * CAP + l2;
            if (haveComb) comb[idx] = g2 / denom;
            if (haveDisp) disp[idx] = 1.0f;
        }
    }
    // l_aux from block 0
    if (blockIdx.x == 0) {
        __shared__ float sm[NEXP];
        if (threadIdx.x < NEXP) {
            const int e = threadIdx.x;
            float s = 0.f;
            for (int b = 0; b < GEMM_BLOCKS; b++) s += g_me_part[b * NEXP + e];
            float me = s * (1.0f / NTOK);
            float ce = (float)g_cnt1[e] * (1.0f / NTOK);
            sm[e] = me * ce;
        }
        __syncthreads();
        if (threadIdx.x == 0) {
            float tot = 0.f;
            for (int i = 0; i < NEXP; i++) tot += sm[i];
            out[0] = tot * (float)NEXP;
        }
    }
}

// ---------------- launch ----------------
extern "C" void kernel_launch(void* const* d_in, const int* in_sizes, int n_in,
                              void* d_out, int out_size) {
    const float* x  = (const float*)d_in[0];
    const float* wg = (const float*)d_in[1];
    float* out = (float*)d_out;

    fused_kernel<<<TOTAL_BLOCKS, 256>>>(x, wg, out, out_size);
    cumsum_kernel<<<NEXP, 256>>>();
    scatter_laux_kernel<<<NTOK / 256, 256>>>(out, out_size);
}

// round 4
// speedup vs baseline: 1.3203x; 1.1417x over previous
#include <cuda_runtime.h>
#include <cstdint>
#include <cstddef>

#define NTOK 8192
#define NEXP 64
#define MDIM 2048
#define CAP  256
#define SEC  134217728LL   // 8192*64*256

#define GEMM_BLOCKS 128
#define FILL_BLOCKS 464
#define TOTAL_BLOCKS (GEMM_BLOCKS + FILL_BLOCKS)   // 592 = 4 * 148
#define CHUNK_BYTES 32768
#define N_CHUNKS 32768            // 2^30 bytes = full output minus 4-byte tail
#define CHUNKS_PER_BLOCK 71       // ceil(32768/464)

// ---------------- device scratch ----------------
__device__ int    g_e12[NTOK];           // e1 | e2<<8
__device__ float2 g_g12[NTOK];           // raw gate values (g1, g2)
__device__ int    g_loc1[NTOK];
__device__ int    g_loc2[NTOK];          // partial (needs +cnt1[e2])
__device__ int    g_cnt1[NEXP];
__device__ float  g_me_part[GEMM_BLOCKS * NEXP];

// ---------------- threefry2x32, key (0,42), partitionable fold ----------------
__device__ __forceinline__ uint2 threefry2x32_k42(uint32_t x0, uint32_t x1) {
    const uint32_t k0 = 0u, k1 = 42u;
    const uint32_t k2 = k0 ^ k1 ^ 0x1BD11BDAu;
    x0 += k0; x1 += k1;
#define TFR(r) { x0 += x1; x1 = (x1 << (r)) | (x1 >> (32 - (r))); x1 ^= x0; }
    TFR(13) TFR(15) TFR(26) TFR(6)   x0 += k1; x1 += k2 + 1u;
    TFR(17) TFR(29) TFR(16) TFR(24)  x0 += k2; x1 += k0 + 2u;
    TFR(13) TFR(15) TFR(26) TFR(6)   x0 += k0; x1 += k1 + 3u;
    TFR(17) TFR(29) TFR(16) TFR(24)  x0 += k1; x1 += k2 + 4u;
    TFR(13) TFR(15) TFR(26) TFR(6)   x0 += k2; x1 += k0 + 5u;
#undef TFR
    return make_uint2(x0, x1);
}

__device__ __forceinline__ float gumbel_from_flat(uint32_t flat) {
    uint2 r = threefry2x32_k42(0u, flat);
    uint32_t bits = r.x ^ r.y;
    float u = __uint_as_float((bits >> 9) | 0x3f800000u) - 1.0f;
    const float tiny = 1.17549435082228751e-38f;
    u = u * (1.0f - tiny) + tiny;
    u = fmaxf(tiny, u);
    return -logf(-logf(u));
}

// ---------------- Kernel 1: fused GEMM+gating (blocks 0..127) + TMA bulk zero-fill ----
__global__ void __launch_bounds__(256) fused_kernel(const float* __restrict__ X,
                                                    const float* __restrict__ W,
                                                    float* __restrict__ out, int out_size) {
    __shared__ float pool[8448];   // 33 KB; fill path uses first 32KB, GEMM uses ~18.7KB
    const int bid = blockIdx.x;
    const int tid = threadIdx.x;

    if (bid >= GEMM_BLOCKS) {
        // -------- bulk-async zero-fill path --------
        const int fb = bid - GEMM_BLOCKS;
        float4* s4 = (float4*)pool;
        float4 z = make_float4(0.f, 0.f, 0.f, 0.f);
#pragma unroll
        for (int i = 0; i < 8; i++) s4[tid + 256 * i] = z;
        __syncthreads();

        if (tid == 0) {
            asm volatile("fence.proxy.async.shared::cta;" ::: "memory");
            uint32_t saddr;
            asm("{ .reg .u64 t; cvta.to.shared.u64 t, %1; cvt.u32.u64 %0, t; }"
                : "=r"(saddr) : "l"(pool));
            long long c0 = (long long)fb * CHUNKS_PER_BLOCK;
            long long c1 = c0 + CHUNKS_PER_BLOCK;
            if (c1 > N_CHUNKS) c1 = N_CHUNKS;
            for (long long c = c0; c < c1; ++c) {
                char* g = (char*)out + (c << 15);
                asm volatile("cp.async.bulk.global.shared::cta.bulk_group [%0], [%1], %2;"
                             :: "l"(g), "r"(saddr), "r"((int)CHUNK_BYTES) : "memory");
                asm volatile("cp.async.bulk.commit_group;" ::: "memory");
                asm volatile("cp.async.bulk.wait_group.read 8;" ::: "memory");
            }
            asm volatile("cp.async.bulk.wait_group 0;" ::: "memory");
        }
        if (fb == 0 && tid == 1) out[out_size - 1] = 0.f;   // 4-byte tail
        __syncthreads();
        return;
    }

    // -------- GEMM path: 64 tokens x 64 experts --------
    float (*sx)[68] = (float(*)[68])pool;              // 32 x 68
    float (*sw)[68] = (float(*)[68])(pool + 32 * 68);  // 32 x 68
    float* lgs   = pool;                               // 64 x 65 (reuse)
    float* gpart = pool + 64 * 65;                     // 8 x 64

    const int tb = bid * 64;
    const int tx = tid & 15;   // expert quad
    const int ty = tid >> 4;   // token quad

    float acc[4][4];
#pragma unroll
    for (int i = 0; i < 4; i++)
#pragma unroll
        for (int j = 0; j < 4; j++) acc[i][j] = 0.f;

    for (int kk = 0; kk < MDIM; kk += 32) {
#pragma unroll
        for (int i = 0; i < 2; i++) {
            int idx = tid + 256 * i;
            int row = idx >> 3;
            int kq  = (idx & 7) * 4;
            float4 vx = *(const float4*)&X[(size_t)(tb + row) * MDIM + kk + kq];
            sx[kq + 0][row] = vx.x; sx[kq + 1][row] = vx.y;
            sx[kq + 2][row] = vx.z; sx[kq + 3][row] = vx.w;
            float4 vw = *(const float4*)&W[(size_t)row * MDIM + kk + kq];
            sw[kq + 0][row] = vw.x; sw[kq + 1][row] = vw.y;
            sw[kq + 2][row] = vw.z; sw[kq + 3][row] = vw.w;
        }
        __syncthreads();
#pragma unroll
        for (int k = 0; k < 32; k++) {
            float4 a = *(const float4*)&sx[k][ty * 4];
            float4 b = *(const float4*)&sw[k][tx * 4];
            float av[4] = {a.x, a.y, a.z, a.w};
            float bv[4] = {b.x, b.y, b.z, b.w};
#pragma unroll
            for (int i = 0; i < 4; i++)
#pragma unroll
                for (int j = 0; j < 4; j++) acc[i][j] += av[i] * bv[j];
        }
        __syncthreads();
    }

#pragma unroll
    for (int i = 0; i < 4; i++)
#pragma unroll
        for (int j = 0; j < 4; j++)
            lgs[(ty * 4 + i) * 65 + tx * 4 + j] = acc[i][j];
    __syncthreads();

    // -------- gating: warp w handles tokens w*8 .. w*8+7 --------
    const unsigned FULL = 0xffffffffu;
    const int w = tid >> 5;
    const int lane = tid & 31;
    float accx = 0.f, accy = 0.f;

#pragma unroll 1
    for (int k = 0; k < 8; k++) {
        const int tl = w * 8 + k;
        const int t  = tb + tl;
        float l0 = lgs[tl * 65 + lane * 2];
        float l1 = lgs[tl * 65 + lane * 2 + 1];

        float vmax = fmaxf(l0, l1);
#pragma unroll
        for (int o = 16; o; o >>= 1) vmax = fmaxf(vmax, __shfl_xor_sync(FULL, vmax, o));

        float bv; int bi;
        if (l0 >= l1) { bv = l0; bi = lane * 2; } else { bv = l1; bi = lane * 2 + 1; }
#pragma unroll
        for (int o = 16; o; o >>= 1) {
            float ov = __shfl_xor_sync(FULL, bv, o);
            int   oi = __shfl_xor_sync(FULL, bi, o);
            if (ov > bv || (ov == bv && oi < bi)) { bv = ov; bi = oi; }
        }
        const int e1 = bi;

        float ex0 = expf(l0 - vmax), ex1 = expf(l1 - vmax);
        float ssum = ex0 + ex1;
#pragma unroll
        for (int o = 16; o; o >>= 1) ssum += __shfl_xor_sync(FULL, ssum, o);
        float gx = ex0 / ssum, gy = ex1 / ssum;
        accx += gx; accy += gy;

        uint32_t f0 = (uint32_t)t * NEXP + lane * 2;
        float n0 = l0 + gumbel_from_flat(f0);
        float n1 = l1 + gumbel_from_flat(f0 + 1);
        if (lane * 2     == e1) n0 = -__int_as_float(0x7f800000);
        if (lane * 2 + 1 == e1) n1 = -__int_as_float(0x7f800000);

        float cv; int ci;
        if (n0 >= n1) { cv = n0; ci = lane * 2; } else { cv = n1; ci = lane * 2 + 1; }
#pragma unroll
        for (int o = 16; o; o >>= 1) {
            float ov = __shfl_xor_sync(FULL, cv, o);
            int   oi = __shfl_xor_sync(FULL, ci, o);
            if (ov > cv || (ov == cv && oi < ci)) { cv = ov; ci = oi; }
        }
        const int e2 = ci;

        float ge1 = __shfl_sync(FULL, (e1 & 1) ? gy : gx, e1 >> 1);
        float ge2 = __shfl_sync(FULL, (e2 & 1) ? gy : gx, e2 >> 1);

        if (lane == 0) {
            g_e12[t] = e1 | (e2 << 8);
            g_g12[t] = make_float2(ge1, ge2);
        }
    }

    gpart[w * 64 + lane * 2]     = accx;
    gpart[w * 64 + lane * 2 + 1] = accy;
    __syncthreads();
    if (tid < NEXP) {
        float s = 0.f;
#pragma unroll
        for (int i = 0; i < 8; i++) s += gpart[i * 64 + tid];
        g_me_part[bid * NEXP + tid] = s;
    }
}

// ---------------- Kernel 2: single-pass dual cumsum (rank1 + rank2) ----------------
__global__ void __launch_bounds__(256) cumsum_kernel() {
    const unsigned FULL = 0xffffffffu;
    const int Eid = blockIdx.x;
    const int tid = threadIdx.x;
    const int w = tid >> 5;
    const int lane = tid & 31;
    __shared__ int wtot[8];

    int off1 = 0, off2 = 0;

    for (int base = 0; base < NTOK; base += 1024) {
        int4 v = *(const int4*)&g_e12[base + tid * 4];
        int va[4] = {v.x, v.y, v.z, v.w};
        int f1[4], f2[4], p1[4], p2[4];
        int c1 = 0, c2 = 0;
#pragma unroll
        for (int k = 0; k < 4; k++) {
            f1[k] = ((va[k] & 0xff) == Eid);
            f2[k] = (((va[k] >> 8) & 0xff) == Eid);
            p1[k] = c1; p2[k] = c2;
            c1 += f1[k]; c2 += f2[k];
        }
        int c = c1 | (c2 << 16);
        int incl = c;
#pragma unroll
        for (int o = 1; o < 32; o <<= 1) {
            int n = __shfl_up_sync(FULL, incl, o);
            if (lane >= o) incl += n;
        }
        int excl = incl - c;
        if (lane == 31) wtot[w] = incl;
        __syncthreads();
        int wb = 0, bt = 0;
#pragma unroll
        for (int i = 0; i < 8; i++) { int t = wtot[i]; if (i < w) wb += t; bt += t; }
        int pk = wb + excl;
        int b1 = off1 + (pk & 0xffff);
        int b2 = off2 + ((pk >> 16) & 0xffff);
#pragma unroll
        for (int k = 0; k < 4; k++) {
            int tok = base + tid * 4 + k;
            if (f1[k]) g_loc1[tok] = b1 + p1[k];
            if (f2[k]) g_loc2[tok] = b2 + p2[k];
        }
        off1 += bt & 0xffff;
        off2 += (bt >> 16) & 0xffff;
        __syncthreads();
    }
    if (tid == 0) g_cnt1[Eid] = off1;
}

// ---------------- Kernel 3: scatter + l_aux ----------------
__global__ void __launch_bounds__(256) scatter_laux_kernel(float* __restrict__ out, int out_size) {
    const int t = blockIdx.x * 256 + threadIdx.x;
    if (t < NTOK) {
        int e12 = g_e12[t];
        const int e1 = e12 & 0xff, e2 = (e12 >> 8) & 0xff;
        const int l1 = g_loc1[t];
        const int l2 = g_loc2[t] + g_cnt1[e2];
        const bool k1 = (l1 < CAP), k2 = (l2 < CAP);
        float2 g12 = g_g12[t];
        const float g1 = k1 ? g12.x : 0.f;
        const float g2 = k2 ? g12.y : 0.f;
        const float denom = fmaxf(g1 + g2, 1.1920928955078125e-7f);

        const bool haveComb = ((long long)out_size >= 1 + SEC);
        const bool haveDisp = ((long long)out_size >= 1 + 2 * SEC);
        float* comb = out + 1;
        float* disp = out + 1 + SEC;

        if (k1) {
            size_t idx = (size_t)t * (NEXP * CAP) + (size_t)e1 * CAP + l1;
            if (haveComb) comb[idx] = g1 / denom;
            if (haveDisp) disp[idx] = 1.0f;
        }
        if (k2) {
            size_t idx = (size_t)t * (NEXP * CAP) + (size_t)e2 * CAP + l2;
            if (haveComb) comb[idx] = g2 / denom;
            if (haveDisp) disp[idx] = 1.0f;
        }
    }
    if (blockIdx.x == 0) {
        __shared__ float sm[NEXP];
        if (threadIdx.x < NEXP) {
            const int e = threadIdx.x;
            float s = 0.f;
            for (int b = 0; b < GEMM_BLOCKS; b++) s += g_me_part[b * NEXP + e];
            float me = s * (1.0f / NTOK);
            float ce = (float)g_cnt1[e] * (1.0f / NTOK);
            sm[e] = me * ce;
        }
        __syncthreads();
        if (threadIdx.x == 0) {
            float tot = 0.f;
            for (int i = 0; i < NEXP; i++) tot += sm[i];
            out[0] = tot * (float)NEXP;
        }
    }
}

// ---------------- launch ----------------
extern "C" void kernel_launch(void* const* d_in, const int* in_sizes, int n_in,
                              void* d_out, int out_size) {
    const float* x  = (const float*)d_in[0];
    const float* wg = (const float*)d_in[1];
    float* out = (float*)d_out;

    fused_kernel<<<TOTAL_BLOCKS, 256>>>(x, wg, out, out_size);
    cumsum_kernel<<<NEXP, 256>>>();
    scatter_laux_kernel<<<NTOK / 256, 256>>>(out, out_size);
}